// round 2
// baseline (speedup 1.0000x reference)
#include <cuda_runtime.h>
#include <cuda_bf16.h>

// ---------------------------------------------------------------------------
// SAGE 2-layer forward, GB300 sm_103a
//   L1: h  = relu( mean_agg(x) @ W1l + b1 + x @ W1r )        (d=128)
//   L2: out= mean_agg(h@W2l) + b2 + h @ W2r                  (linearity: project
//       to 64 BEFORE the edge pass -> half the scatter traffic)
// NOTE: edge_index is int32 on device (JAX x64 disabled downgrades int64->int32).
// ---------------------------------------------------------------------------

#define N_NODES 50000
#define N_EDGES 800000
#define IN_C    128
#define HID_C   128
#define OUT_C   64

// Scratch (static __device__ arrays; no runtime allocation)
__device__ __align__(16) float g_msg1[(size_t)N_NODES * HID_C];   // 25.6 MB
__device__ __align__(16) float g_deg [N_NODES];
__device__ __align__(16) float g_h   [(size_t)N_NODES * HID_C];   // 25.6 MB
__device__ __align__(16) float g_c2  [(size_t)N_NODES * 128];     // cols 0..63 = h@W2l, 64..127 = h@W2r
__device__ __align__(16) float g_msg2[(size_t)N_NODES * OUT_C];   // 12.8 MB

__device__ __forceinline__ void red_add_v4(float* addr, float4 v) {
    asm volatile("red.global.add.v4.f32 [%0], {%1,%2,%3,%4};"
                 :: "l"(addr), "f"(v.x), "f"(v.y), "f"(v.z), "f"(v.w)
                 : "memory");
}

// ---------------------------------------------------------------------------
// Zero the accumulators (deterministic; runs first every launch)
// ---------------------------------------------------------------------------
__global__ void zero_kernel() {
    const float4 z = make_float4(0.f, 0.f, 0.f, 0.f);
    int tid = blockIdx.x * blockDim.x + threadIdx.x;
    int stride = gridDim.x * blockDim.x;
    float4* m1 = (float4*)g_msg1;
    for (int i = tid; i < N_NODES * HID_C / 4; i += stride) m1[i] = z;
    float4* m2 = (float4*)g_msg2;
    for (int i = tid; i < N_NODES * OUT_C / 4; i += stride) m2[i] = z;
    float4* dg = (float4*)g_deg;
    for (int i = tid; i < N_NODES / 4; i += stride) dg[i] = z;
}

// ---------------------------------------------------------------------------
// Layer-1 edge scatter: one warp per edge, d=128 (32 x float4)
// also accumulates degree (lane 0). Indices are int32.
// ---------------------------------------------------------------------------
__global__ void scatter1_kernel(const float* __restrict__ x,
                                const int* __restrict__ ei) {
    int gtid = blockIdx.x * blockDim.x + threadIdx.x;
    int e    = gtid >> 5;
    int lane = gtid & 31;
    if (e >= N_EDGES) return;

    int src = __ldg(ei + e);
    int dst = __ldg(ei + N_EDGES + e);
    if ((unsigned)src >= N_NODES || (unsigned)dst >= N_NODES) return; // guard

    float4 v = __ldg((const float4*)(x + (size_t)src * IN_C) + lane);
    red_add_v4(g_msg1 + (size_t)dst * HID_C + lane * 4, v);
    if (lane == 0) atomicAdd(&g_deg[dst], 1.0f);
}

// ---------------------------------------------------------------------------
// Layer-2 edge scatter: 16 lanes per edge, d=64 (16 x float4)
// gathers the pre-projected t = h @ W2l (= first 64 cols of g_c2)
// ---------------------------------------------------------------------------
__global__ void scatter2_kernel(const int* __restrict__ ei) {
    int gtid = blockIdx.x * blockDim.x + threadIdx.x;
    int e = gtid >> 4;
    int l = gtid & 15;
    if (e >= N_EDGES) return;

    int src = __ldg(ei + e);
    int dst = __ldg(ei + N_EDGES + e);
    if ((unsigned)src >= N_NODES || (unsigned)dst >= N_NODES) return; // guard

    float4 v = __ldg((const float4*)(g_c2 + (size_t)src * 128) + l);
    red_add_v4(g_msg2 + (size_t)dst * OUT_C + l * 4, v);
}

// ---------------------------------------------------------------------------
// SGEMM1: h = relu( [msg1/deg | x] (50000 x 256) @ [W1l ; W1r] (256 x 128) + b1 )
// BM=64, BN=128, BK=32, 256 threads, 8x4 micro-tile per thread.
// ---------------------------------------------------------------------------
__global__ void __launch_bounds__(256) gemm1_kernel(const float* __restrict__ x,
                                                    const float* __restrict__ W1l,
                                                    const float* __restrict__ W1r,
                                                    const float* __restrict__ b1) {
    __shared__ float As[32][68];     // K-major (transposed), padded; row = 272B (16B multiple)
    __shared__ float Bs[32][128];
    __shared__ float rdeg_s[64];

    const int tid = threadIdx.x;
    const int ty  = tid >> 5;        // 0..7  -> rows ty*8 .. ty*8+7
    const int tx  = tid & 31;        // 0..31 -> cols tx*4 .. tx*4+3
    const int rowBase = blockIdx.x * 64;

    if (tid < 64) {
        int r = rowBase + tid;
        float dv = (r < N_NODES) ? g_deg[r] : 1.0f;
        rdeg_s[tid] = 1.0f / fmaxf(dv, 1.0f);
    }
    __syncthreads();

    float acc[8][4];
    #pragma unroll
    for (int i = 0; i < 8; ++i)
        #pragma unroll
        for (int j = 0; j < 4; ++j) acc[i][j] = 0.f;

    for (int kb = 0; kb < 256; kb += 32) {
        const bool isMsg = (kb < 128);
        // ---- A tile: 64 rows x 32 k, 2 float4 per thread, store transposed
        #pragma unroll
        for (int it = 0; it < 2; ++it) {
            int fid = tid + it * 256;
            int r   = fid >> 3;       // 0..63
            int k4  = fid & 7;        // 0..7
            int grow = rowBase + r;
            float4 v = make_float4(0.f, 0.f, 0.f, 0.f);
            if (grow < N_NODES) {
                if (isMsg) {
                    v = *(const float4*)(g_msg1 + (size_t)grow * 128 + kb + k4 * 4);
                    float s = rdeg_s[r];
                    v.x *= s; v.y *= s; v.z *= s; v.w *= s;
                } else {
                    v = __ldg((const float4*)(x + (size_t)grow * 128 + (kb - 128) + k4 * 4));
                }
            }
            As[k4 * 4 + 0][r] = v.x;
            As[k4 * 4 + 1][r] = v.y;
            As[k4 * 4 + 2][r] = v.z;
            As[k4 * 4 + 3][r] = v.w;
        }
        // ---- B tile: 32 k x 128 n, 4 float4 per thread
        const float* W = isMsg ? W1l : W1r;
        const int kbase = isMsg ? kb : kb - 128;
        #pragma unroll
        for (int it = 0; it < 4; ++it) {
            int fid = tid + it * 256;
            int kk = fid >> 5;
            int j4 = fid & 31;
            float4 v = __ldg((const float4*)(W + (size_t)(kbase + kk) * 128 + j4 * 4));
            *(float4*)&Bs[kk][j4 * 4] = v;
        }
        __syncthreads();

        #pragma unroll
        for (int kk = 0; kk < 32; ++kk) {
            float4 a0 = *(const float4*)&As[kk][ty * 8];
            float4 a1 = *(const float4*)&As[kk][ty * 8 + 4];
            float4 b  = *(const float4*)&Bs[kk][tx * 4];
            float a[8] = {a0.x, a0.y, a0.z, a0.w, a1.x, a1.y, a1.z, a1.w};
            float bv[4] = {b.x, b.y, b.z, b.w};
            #pragma unroll
            for (int i = 0; i < 8; ++i)
                #pragma unroll
                for (int j = 0; j < 4; ++j)
                    acc[i][j] = fmaf(a[i], bv[j], acc[i][j]);
        }
        __syncthreads();
    }

    float4 bb = __ldg((const float4*)(b1 + tx * 4));
    float bj[4] = {bb.x, bb.y, bb.z, bb.w};
    #pragma unroll
    for (int i = 0; i < 8; ++i) {
        int r = rowBase + ty * 8 + i;
        if (r < N_NODES) {
            float4 o;
            o.x = fmaxf(acc[i][0] + bj[0], 0.f);
            o.y = fmaxf(acc[i][1] + bj[1], 0.f);
            o.z = fmaxf(acc[i][2] + bj[2], 0.f);
            o.w = fmaxf(acc[i][3] + bj[3], 0.f);
            *(float4*)(g_h + (size_t)r * 128 + tx * 4) = o;
        }
    }
}

// ---------------------------------------------------------------------------
// SGEMM2: c2 = h (50000 x 128) @ [W2l | W2r] (128 x 128, column-concat)
// cols 0..63 -> t = h@W2l (scattered next), cols 64..127 -> hr = h@W2r
// ---------------------------------------------------------------------------
__global__ void __launch_bounds__(256) gemm2_kernel(const float* __restrict__ W2l,
                                                    const float* __restrict__ W2r) {
    __shared__ float As[32][68];
    __shared__ float Bs[32][128];

    const int tid = threadIdx.x;
    const int ty  = tid >> 5;
    const int tx  = tid & 31;
    const int rowBase = blockIdx.x * 64;

    float acc[8][4];
    #pragma unroll
    for (int i = 0; i < 8; ++i)
        #pragma unroll
        for (int j = 0; j < 4; ++j) acc[i][j] = 0.f;

    for (int kb = 0; kb < 128; kb += 32) {
        #pragma unroll
        for (int it = 0; it < 2; ++it) {
            int fid = tid + it * 256;
            int r   = fid >> 3;
            int k4  = fid & 7;
            int grow = rowBase + r;
            float4 v = make_float4(0.f, 0.f, 0.f, 0.f);
            if (grow < N_NODES)
                v = *(const float4*)(g_h + (size_t)grow * 128 + kb + k4 * 4);
            As[k4 * 4 + 0][r] = v.x;
            As[k4 * 4 + 1][r] = v.y;
            As[k4 * 4 + 2][r] = v.z;
            As[k4 * 4 + 3][r] = v.w;
        }
        // B tile: column-concat of W2l (j4 0..15) and W2r (j4 16..31), each 128x64
        #pragma unroll
        for (int it = 0; it < 4; ++it) {
            int fid = tid + it * 256;
            int kk = fid >> 5;
            int j4 = fid & 31;
            float4 v;
            if (j4 < 16)
                v = __ldg((const float4*)(W2l + (size_t)(kb + kk) * 64 + j4 * 4));
            else
                v = __ldg((const float4*)(W2r + (size_t)(kb + kk) * 64 + (j4 - 16) * 4));
            *(float4*)&Bs[kk][j4 * 4] = v;
        }
        __syncthreads();

        #pragma unroll
        for (int kk = 0; kk < 32; ++kk) {
            float4 a0 = *(const float4*)&As[kk][ty * 8];
            float4 a1 = *(const float4*)&As[kk][ty * 8 + 4];
            float4 b  = *(const float4*)&Bs[kk][tx * 4];
            float a[8] = {a0.x, a0.y, a0.z, a0.w, a1.x, a1.y, a1.z, a1.w};
            float bv[4] = {b.x, b.y, b.z, b.w};
            #pragma unroll
            for (int i = 0; i < 8; ++i)
                #pragma unroll
                for (int j = 0; j < 4; ++j)
                    acc[i][j] = fmaf(a[i], bv[j], acc[i][j]);
        }
        __syncthreads();
    }

    #pragma unroll
    for (int i = 0; i < 8; ++i) {
        int r = rowBase + ty * 8 + i;
        if (r < N_NODES) {
            float4 o = make_float4(acc[i][0], acc[i][1], acc[i][2], acc[i][3]);
            *(float4*)(g_c2 + (size_t)r * 128 + tx * 4) = o;
        }
    }
}

// ---------------------------------------------------------------------------
// Final epilogue: out = msg2/deg + b2 + hr
// ---------------------------------------------------------------------------
__global__ void final_kernel(float* __restrict__ out, const float* __restrict__ b2) {
    int i = blockIdx.x * blockDim.x + threadIdx.x;
    if (i >= N_NODES * OUT_C) return;
    int n = i >> 6;
    int j = i & 63;
    float d = fmaxf(g_deg[n], 1.0f);
    out[i] = g_msg2[i] / d + __ldg(b2 + j) + g_c2[(size_t)n * 128 + 64 + j];
}

// ---------------------------------------------------------------------------
extern "C" void kernel_launch(void* const* d_in, const int* in_sizes, int n_in,
                              void* d_out, int out_size) {
    const float* x   = (const float*)d_in[0];
    const int*   ei  = (const int*)d_in[1];     // int32 (JAX x64 disabled)
    const float* W1l = (const float*)d_in[2];
    const float* b1  = (const float*)d_in[3];
    const float* W1r = (const float*)d_in[4];
    const float* W2l = (const float*)d_in[5];
    const float* b2  = (const float*)d_in[6];
    const float* W2r = (const float*)d_in[7];
    float* out = (float*)d_out;

    zero_kernel<<<2048, 256>>>();
    scatter1_kernel<<<(N_EDGES * 32) / 256, 256>>>(x, ei);

    const int gemmBlocks = (N_NODES + 63) / 64;   // 782
    gemm1_kernel<<<gemmBlocks, 256>>>(x, W1l, W1r, b1);
    gemm2_kernel<<<gemmBlocks, 256>>>(W2l, W2r);

    scatter2_kernel<<<(N_EDGES * 16) / 256, 256>>>(ei);
    final_kernel<<<(N_NODES * OUT_C + 255) / 256, 256>>>(out, b2);
}